// round 17
// baseline (speedup 1.0000x reference)
#include <cuda_runtime.h>
#include <cuda_bf16.h>
#include <cuda_fp16.h>
#include <cstdint>

// ---------------------------------------------------------------------------
// Problem: B=16, S=512, F=512, H=8, D=512.
// Logit path: GT_h = Wk_h x Wq_h^T; Y_z = x_b GT_h^T; logits = Y_z x_b^T.
//   All bf16 hi/lo 3-term emulation (precision floor).
// V path: single-pass fp16 proj (fused transpose) + 1-pass fp16 PV.
// R17: wt_v merged into gt launch; softmax 2 rows/block.
// ---------------------------------------------------------------------------
__device__ float g_P[128 * 512 * 512];      // scores fp32 (softmax input)

__device__ __nv_bfloat16 g_xh[8192 * 512],   g_xl[8192 * 512];
__device__ __nv_bfloat16 g_wqh[512 * 4096],  g_wql[512 * 4096];
__device__ __nv_bfloat16 g_wkh[512 * 4096],  g_wkl[512 * 4096];
__device__ __nv_bfloat16 g_GTh[8 * 512 * 512],   g_GTl[8 * 512 * 512];
__device__ __nv_bfloat16 g_Yh[128 * 512 * 512],  g_Yl[128 * 512 * 512];

__device__ __half g_x16[8192 * 512];        // x, single fp16 plane
__device__ __half g_WV16[4096 * 512];       // wv^T, single fp16 plane
__device__ __half g_VT[128 * 512 * 512];    // V^T per (h,b): [z][d][j], fp16
__device__ __half g_Pf[128 * 512 * 512];    // softmax probs fp16

// ===========================================================================
// Helpers
// ===========================================================================
__device__ __forceinline__ uint32_t smem_u32(const void* p) {
    uint32_t a;
    asm("{ .reg .u64 t; cvta.to.shared.u64 t, %1; cvt.u32.u64 %0, t; }"
        : "=r"(a) : "l"(p));
    return a;
}

__device__ __forceinline__ void cp16(uint32_t dst, const void* src) {
    asm volatile("cp.async.cg.shared.global [%0], [%1], 16;"
                 :: "r"(dst), "l"(src) : "memory");
}
#define CP_COMMIT() asm volatile("cp.async.commit_group;" ::: "memory")
#define CP_WAIT1()  asm volatile("cp.async.wait_group 1;" ::: "memory")

// pack two fp32 into bf16x2 hi-plane word + lo-plane word (rn rounding)
__device__ __forceinline__ void pack2(float x0, float x1, uint32_t& h, uint32_t& l) {
    asm("cvt.rn.bf16x2.f32 %0, %1, %2;" : "=r"(h) : "f"(x1), "f"(x0));
    float f0 = __uint_as_float(h << 16);
    float f1 = __uint_as_float(h & 0xFFFF0000u);
    float l0 = x0 - f0, l1 = x1 - f1;
    asm("cvt.rn.bf16x2.f32 %0, %1, %2;" : "=r"(l) : "f"(l1), "f"(l0));
}

// D += A * B : m16n8k16 bf16, row.col, fp32 accumulate
__device__ __forceinline__ void mma16(float* c, const uint32_t* a, const uint32_t* b) {
    asm volatile(
        "mma.sync.aligned.m16n8k16.row.col.f32.bf16.bf16.f32 "
        "{%0,%1,%2,%3}, {%4,%5,%6,%7}, {%8,%9}, {%0,%1,%2,%3};"
        : "+f"(c[0]), "+f"(c[1]), "+f"(c[2]), "+f"(c[3])
        : "r"(a[0]), "r"(a[1]), "r"(a[2]), "r"(a[3]), "r"(b[0]), "r"(b[1]));
}

// D += A * B : m16n8k16 fp16, row.col, fp32 accumulate
__device__ __forceinline__ void mma16f(float* c, const uint32_t* a, const uint32_t* b) {
    asm volatile(
        "mma.sync.aligned.m16n8k16.row.col.f32.f16.f16.f32 "
        "{%0,%1,%2,%3}, {%4,%5,%6,%7}, {%8,%9}, {%0,%1,%2,%3};"
        : "+f"(c[0]), "+f"(c[1]), "+f"(c[2]), "+f"(c[3])
        : "r"(a[0]), "r"(a[1]), "r"(a[2]), "r"(a[3]), "r"(b[0]), "r"(b[1]));
}

__device__ __forceinline__ void ldsm4(uint32_t* r, uint32_t addr) {
    asm volatile("ldmatrix.sync.aligned.m8n8.x4.shared.b16 {%0,%1,%2,%3}, [%4];"
                 : "=r"(r[0]), "=r"(r[1]), "=r"(r[2]), "=r"(r[3]) : "r"(addr));
}

// ===========================================================================
// NT GEMM on bf16 hi/lo planes (3-term emulation), 256 threads. [R10 core]
//   C[128x64] tile, 8 warps 4(M)x2(N), warp tile 32x32, 3 CTAs/SM. K=512.
// ===========================================================================
#define KB        32
#define NKB       16
#define STAGE     24576
#define GEMM_SMEM (3 * STAGE)   // 73728

template <int EPI>   // 0: fp32 C ; 1: bf16 hi/lo planes
__device__ __forceinline__ void gemm_nt_bf16(
    const __nv_bfloat16* __restrict__ Ah, const __nv_bfloat16* __restrict__ Al, int lda,
    const __nv_bfloat16* __restrict__ Bh, const __nv_bfloat16* __restrict__ Bl, int ldb,
    float* __restrict__ C, __nv_bfloat16* __restrict__ Ch,
    __nv_bfloat16* __restrict__ Cl, int ldc, int by, int bx)
{
    extern __shared__ __align__(128) char smc[];
    const uint32_t sa = smem_u32(smc);

    const int tid = threadIdx.x;
    const int wid = tid >> 5;
    const int lid = tid & 31;
    const int wr  = wid >> 1;          // 0..3 (M)
    const int wc  = wid & 1;           // 0..1 (N)
    const int g   = lid >> 2;
    const int tg  = lid & 3;

    const __nv_bfloat16* Abh = Ah + (size_t)(by * 128) * lda;
    const __nv_bfloat16* Abl = Al + (size_t)(by * 128) * lda;
    const __nv_bfloat16* Bbh = Bh + (size_t)(bx * 64) * ldb;
    const __nv_bfloat16* Bbl = Bl + (size_t)(bx * 64) * ldb;

    auto load_stage = [&](int buf, int kb) {
        const uint32_t dbase = sa + buf * STAGE;
        const int kc = kb * KB;
#pragma unroll
        for (int i = 0; i < 4; ++i) {               // A: 1024 chunks
            const int t = tid + (i << 8);
            const int row = t >> 3, c = t & 7;
            const __nv_bfloat16* src =
                ((c & 4) ? Abl : Abh) + (size_t)row * lda + kc + (c & 3) * 8;
            cp16(dbase + row * 128 + ((c ^ (row & 7)) << 4), src);
        }
        {
            const int t = tid + 1024;
            const int row = (t >> 3) & 63, c = t & 7;
            const __nv_bfloat16* src =
                ((c & 4) ? Bbl : Bbh) + (size_t)row * ldb + kc + (c & 3) * 8;
            cp16(dbase + 16384 + row * 128 + ((c ^ (row & 7)) << 4), src);
        }
        {
            const int t = tid + 1280;
            const int row = (t >> 3) & 63, c = t & 7;
            const __nv_bfloat16* src =
                ((c & 4) ? Bbl : Bbh) + (size_t)row * ldb + kc + (c & 3) * 8;
            cp16(dbase + 16384 + row * 128 + ((c ^ (row & 7)) << 4), src);
        }
    };

    float acc[2][4][4];
#pragma unroll
    for (int mt = 0; mt < 2; ++mt)
#pragma unroll
        for (int nt = 0; nt < 4; ++nt)
#pragma unroll
            for (int i = 0; i < 4; ++i) acc[mt][nt][i] = 0.0f;

    const uint32_t sx = (uint32_t)(lid & 7) << 4;
    const uint32_t hb = (uint32_t)(lid >> 4) << 4;
    uint32_t ra[2], rb[2];
#pragma unroll
    for (int mt = 0; mt < 2; ++mt)
        ra[mt] = (uint32_t)(wr * 32 + mt * 16 + (lid & 15)) * 128;
#pragma unroll
    for (int n2 = 0; n2 < 2; ++n2)
        rb[n2] = 16384u + (uint32_t)(wc * 32 + n2 * 16 + (lid & 15)) * 128;

    load_stage(0, 0); CP_COMMIT();
    load_stage(1, 1); CP_COMMIT();

#pragma unroll 1
    for (int kb = 0; kb < NKB; ++kb) {
        CP_WAIT1();
        __syncthreads();
        if (kb + 2 < NKB) load_stage((kb + 2) % 3, kb + 2);
        CP_COMMIT();

        const uint32_t sbase = sa + (kb % 3) * STAGE;

#pragma unroll
        for (int ks = 0; ks < 2; ++ks) {
            const uint32_t cvh = (uint32_t)(ks << 5) + hb;
            const uint32_t cvl = cvh + 64;

            uint32_t ah[2][4], al[2][4], bb[4][2];
#pragma unroll
            for (int mt = 0; mt < 2; ++mt) {
                ldsm4(ah[mt], sbase + ra[mt] + (cvh ^ sx));
                ldsm4(al[mt], sbase + ra[mt] + (cvl ^ sx));
            }
#pragma unroll
            for (int n2 = 0; n2 < 2; ++n2) {
                uint32_t r[4];
                ldsm4(r, sbase + rb[n2] + (cvh ^ sx));
                bb[n2 * 2][0] = r[0]; bb[n2 * 2][1] = r[2];
                bb[n2 * 2 + 1][0] = r[1]; bb[n2 * 2 + 1][1] = r[3];
            }
#pragma unroll
            for (int mt = 0; mt < 2; ++mt)
#pragma unroll
                for (int nt = 0; nt < 4; ++nt) mma16(acc[mt][nt], ah[mt], bb[nt]);
#pragma unroll
            for (int mt = 0; mt < 2; ++mt)
#pragma unroll
                for (int nt = 0; nt < 4; ++nt) mma16(acc[mt][nt], al[mt], bb[nt]);
#pragma unroll
            for (int n2 = 0; n2 < 2; ++n2) {
                uint32_t r[4];
                ldsm4(r, sbase + rb[n2] + (cvl ^ sx));
                bb[n2 * 2][0] = r[0]; bb[n2 * 2][1] = r[2];
                bb[n2 * 2 + 1][0] = r[1]; bb[n2 * 2 + 1][1] = r[3];
            }
#pragma unroll
            for (int mt = 0; mt < 2; ++mt)
#pragma unroll
                for (int nt = 0; nt < 4; ++nt) mma16(acc[mt][nt], ah[mt], bb[nt]);
        }
    }

    const int rbase = by * 128 + wr * 32 + g;
    const int cbase = bx * 64 + wc * 32 + tg * 2;
#pragma unroll
    for (int mt = 0; mt < 2; ++mt) {
#pragma unroll
        for (int nt = 0; nt < 4; ++nt) {
            const int r = rbase + mt * 16;
            const int c = cbase + nt * 8;
            if (EPI == 0) {
                *reinterpret_cast<float2*>(&C[(size_t)r * ldc + c]) =
                    make_float2(acc[mt][nt][0], acc[mt][nt][1]);
                *reinterpret_cast<float2*>(&C[(size_t)(r + 8) * ldc + c]) =
                    make_float2(acc[mt][nt][2], acc[mt][nt][3]);
            } else {
                uint32_t h, l;
                pack2(acc[mt][nt][0], acc[mt][nt][1], h, l);
                *reinterpret_cast<uint32_t*>(Ch + (size_t)r * ldc + c) = h;
                *reinterpret_cast<uint32_t*>(Cl + (size_t)r * ldc + c) = l;
                pack2(acc[mt][nt][2], acc[mt][nt][3], h, l);
                *reinterpret_cast<uint32_t*>(Ch + (size_t)(r + 8) * ldc + c) = h;
                *reinterpret_cast<uint32_t*>(Cl + (size_t)(r + 8) * ldc + c) = l;
            }
        }
    }
}

// ===========================================================================
// fp16 single-pass NT GEMM body (proj_v / pv). C tile 128x64. [R14 core]
// ===========================================================================
template <int EPI>
__device__ __forceinline__ void gemm_nt_f16(
    const __half* __restrict__ Ab, const __half* __restrict__ Bb,
    float* __restrict__ C, int ldc, __half* __restrict__ VT,
    int rloc0, int cloc0)
{
    extern __shared__ __align__(128) char smc[];
    const uint32_t sa = smem_u32(smc);

    const int tid = threadIdx.x;
    const int wid = tid >> 5;
    const int lid = tid & 31;
    const int wr  = wid >> 1;
    const int wc  = wid & 1;
    const int g   = lid >> 2;
    const int tg  = lid & 3;

    auto load_stage = [&](int buf, int kb) {
        const uint32_t dbase = sa + buf * STAGE;
        const int kc = kb * 64;
#pragma unroll
        for (int i = 0; i < 4; ++i) {               // A: 1024 chunks
            const int t = tid + (i << 8);
            const int row = t >> 3, c = t & 7;
            cp16(dbase + row * 128 + ((c ^ (row & 7)) << 4),
                 Ab + (size_t)row * 512 + kc + c * 8);
        }
        {
            const int t = tid;
            const int row = t >> 3, c = t & 7;
            cp16(dbase + 16384 + row * 128 + ((c ^ (row & 7)) << 4),
                 Bb + (size_t)row * 512 + kc + c * 8);
        }
        {
            const int t = tid + 256;
            const int row = t >> 3, c = t & 7;
            cp16(dbase + 16384 + row * 128 + ((c ^ (row & 7)) << 4),
                 Bb + (size_t)row * 512 + kc + c * 8);
        }
    };

    float acc[2][4][4];
#pragma unroll
    for (int mt = 0; mt < 2; ++mt)
#pragma unroll
        for (int nt = 0; nt < 4; ++nt)
#pragma unroll
            for (int i = 0; i < 4; ++i) acc[mt][nt][i] = 0.0f;

    const uint32_t sx = (uint32_t)(lid & 7) << 4;
    const uint32_t hb = (uint32_t)(lid >> 4) << 4;
    uint32_t ra[2], rb[2];
#pragma unroll
    for (int mt = 0; mt < 2; ++mt)
        ra[mt] = (uint32_t)(wr * 32 + mt * 16 + (lid & 15)) * 128;
#pragma unroll
    for (int n2 = 0; n2 < 2; ++n2)
        rb[n2] = 16384u + (uint32_t)(wc * 32 + n2 * 16 + (lid & 15)) * 128;

    load_stage(0, 0); CP_COMMIT();
    load_stage(1, 1); CP_COMMIT();

#pragma unroll 1
    for (int kb = 0; kb < 8; ++kb) {
        CP_WAIT1();
        __syncthreads();
        if (kb + 2 < 8) load_stage((kb + 2) % 3, kb + 2);
        CP_COMMIT();

        const uint32_t sbase = sa + (kb % 3) * STAGE;

#pragma unroll
        for (int ks = 0; ks < 4; ++ks) {
            const uint32_t cv = (uint32_t)(ks << 5) + hb;

            uint32_t ah[2][4], bb[4][2];
#pragma unroll
            for (int mt = 0; mt < 2; ++mt)
                ldsm4(ah[mt], sbase + ra[mt] + (cv ^ sx));
#pragma unroll
            for (int n2 = 0; n2 < 2; ++n2) {
                uint32_t r[4];
                ldsm4(r, sbase + rb[n2] + (cv ^ sx));
                bb[n2 * 2][0] = r[0]; bb[n2 * 2][1] = r[2];
                bb[n2 * 2 + 1][0] = r[1]; bb[n2 * 2 + 1][1] = r[3];
            }
#pragma unroll
            for (int mt = 0; mt < 2; ++mt)
#pragma unroll
                for (int nt = 0; nt < 4; ++nt) mma16f(acc[mt][nt], ah[mt], bb[nt]);
        }
    }

    const int rbase = rloc0 + wr * 32 + g;
    const int cbase = cloc0 + wc * 32 + tg * 2;
#pragma unroll
    for (int mt = 0; mt < 2; ++mt) {
#pragma unroll
        for (int nt = 0; nt < 4; ++nt) {
            const int r = rbase + mt * 16;
            const int c = cbase + nt * 8;
            if (EPI == 0) {
                *reinterpret_cast<float2*>(&C[(size_t)r * ldc + c]) =
                    make_float2(acc[mt][nt][0], acc[mt][nt][1]);
                *reinterpret_cast<float2*>(&C[(size_t)(r + 8) * ldc + c]) =
                    make_float2(acc[mt][nt][2], acc[mt][nt][3]);
            } else {
                __half2 v0 = __floats2half2_rn(acc[mt][nt][0], acc[mt][nt][1]);
                __half2 v1 = __floats2half2_rn(acc[mt][nt][2], acc[mt][nt][3]);
                *reinterpret_cast<__half2*>(VT + (size_t)r * 512 + c)       = v0;
                *reinterpret_cast<__half2*>(VT + (size_t)(r + 8) * 512 + c) = v1;
            }
        }
    }
}

// ===========================================================================
// Merged: id<256 -> GT_h tile (GEMM); id>=256 -> wt_v transpose tile.
// GT_h = Wk_h x Wq_h^T. wt_v: wv[512,4096] -> WV16[4096,512] fp16.
// ===========================================================================
__global__ void __launch_bounds__(256, 3)
gt_wtv(const float* __restrict__ wv)
{
    const int id = blockIdx.x;
    if (id < 256) {
        const int h  = id >> 5;
        const int by = (id >> 3) & 3;
        const int bx = id & 7;
        gemm_nt_bf16<1>(g_wkh + h * 512, g_wkl + h * 512, 4096,
                        g_wqh + h * 512, g_wql + h * 512, 4096,
                        nullptr, g_GTh + (size_t)h * 262144,
                        g_GTl + (size_t)h * 262144, 512, by, bx);
    } else {
        __shared__ float t[32][33];
        const int tl = id - 256;               // 0..2047
        const int n0 = (tl & 127) * 32, k0 = (tl >> 7) * 32;
        const int tx = threadIdx.x & 31, ty = threadIdx.x >> 5;   // 32 x 8
#pragma unroll
        for (int i = 0; i < 4; ++i)
            t[ty + i * 8][tx] = wv[(size_t)(k0 + ty + i * 8) * 4096 + n0 + tx];
        __syncthreads();
#pragma unroll
        for (int i = 0; i < 4; ++i) {
            const float v = t[tx][ty + i * 8];
            g_WV16[(size_t)(n0 + ty + i * 8) * 512 + k0 + tx] = __float2half_rn(v);
        }
    }
}

// ===========================================================================
// Merged: id<4096 -> Y_z = x_b GT_h^T tile (bf16 planes out);
//         id>=4096 -> proj_v fp16 tile (fused transpose into VT).
// ===========================================================================
__global__ void __launch_bounds__(256, 3)
y_projv()
{
    const int id = blockIdx.x;
    if (id < 4096) {
        const int z  = id >> 5;               // h*16 + b
        const int by = (id >> 3) & 3;
        const int bx = id & 7;
        const int h = z >> 4, b = z & 15;
        gemm_nt_bf16<1>(g_xh + (size_t)b * 262144, g_xl + (size_t)b * 262144, 512,
                        g_GTh + (size_t)h * 262144, g_GTl + (size_t)h * 262144, 512,
                        nullptr, g_Yh + (size_t)z * 262144,
                        g_Yl + (size_t)z * 262144, 512, by, bx);
    } else {
        const int t  = id - 4096;             // 0..4095
        const int vx = t & 127;               // token-tile (64 tokens)
        const int vy = t >> 7;                // d-tile (128 dcols)
        const __half* Ab = g_WV16 + (size_t)vy * 128 * 512;
        const __half* Bb = g_x16  + (size_t)vx * 64 * 512;
        const int hH = vy >> 2, bB = vx >> 3;
        __half* VT = g_VT + (size_t)(hH * 16 + bB) * 262144;
        gemm_nt_f16<1>(Ab, Bb, nullptr, 0, VT,
                       (vy & 3) * 128, (vx & 7) * 64);
    }
}

// ===========================================================================
// logits_z = Y_z x_b^T  (fp32 out to g_P)
// ===========================================================================
__global__ void __launch_bounds__(256, 3)
qk2_mm()
{
    const int z = blockIdx.z;                 // h*16 + b
    const int b = z & 15;
    gemm_nt_bf16<0>(g_Yh + (size_t)z * 262144, g_Yl + (size_t)z * 262144, 512,
                    g_xh + (size_t)b * 262144, g_xl + (size_t)b * 262144, 512,
                    g_P + (size_t)z * 262144, nullptr, nullptr, 512,
                    blockIdx.y, blockIdx.x);
}

// ===========================================================================
// PV GEMM: single fp16 P x single fp16 V, 1 MMA pass. C[128x64] fp32.
// ===========================================================================
__global__ void __launch_bounds__(256, 3)
pv_mm(float* __restrict__ out)
{
    const int z = blockIdx.z;
    const int h = z >> 4, b = z & 15;
    const size_t zo = (size_t)z * 262144;
    const __half* Ab = g_Pf + zo + (size_t)(blockIdx.y * 128) * 512;
    const __half* Bb = g_VT + zo + (size_t)(blockIdx.x * 64) * 512;
    float* C = out + (size_t)b * 512 * 4096 + h * 512;
    gemm_nt_f16<0>(Ab, Bb, C, 4096, nullptr,
                   blockIdx.y * 128, blockIdx.x * 64);
}

// ===========================================================================
// Prep: split x -> (xh,xl,x16); wq -> (wqh,wql); wk -> (wkh,wkl). Flat grid.
// ===========================================================================
__global__ void prep_split(const float* __restrict__ x,
                           const float* __restrict__ wq,
                           const float* __restrict__ wk)
{
    const int id = blockIdx.x;
    if (id < 4096) {
        const size_t i = (size_t)id * 1024 + threadIdx.x * 4;
        const float4 v = *reinterpret_cast<const float4*>(x + i);
        uint32_t h0, l0, h1, l1;
        pack2(v.x, v.y, h0, l0);
        pack2(v.z, v.w, h1, l1);
        *reinterpret_cast<uint2*>(g_xh + i) = make_uint2(h0, h1);
        *reinterpret_cast<uint2*>(g_xl + i) = make_uint2(l0, l1);
        *reinterpret_cast<__half2*>(g_x16 + i)     = __floats2half2_rn(v.x, v.y);
        *reinterpret_cast<__half2*>(g_x16 + i + 2) = __floats2half2_rn(v.z, v.w);
    } else if (id < 6144) {
        const size_t i = (size_t)(id - 4096) * 1024 + threadIdx.x * 4;
        const float4 v = *reinterpret_cast<const float4*>(wq + i);
        uint32_t h0, l0, h1, l1;
        pack2(v.x, v.y, h0, l0);
        pack2(v.z, v.w, h1, l1);
        *reinterpret_cast<uint2*>(g_wqh + i) = make_uint2(h0, h1);
        *reinterpret_cast<uint2*>(g_wql + i) = make_uint2(l0, l1);
    } else {
        const size_t i = (size_t)(id - 6144) * 1024 + threadIdx.x * 4;
        const float4 v = *reinterpret_cast<const float4*>(wk + i);
        uint32_t h0, l0, h1, l1;
        pack2(v.x, v.y, h0, l0);
        pack2(v.z, v.w, h1, l1);
        *reinterpret_cast<uint2*>(g_wkh + i) = make_uint2(h0, h1);
        *reinterpret_cast<uint2*>(g_wkl + i) = make_uint2(l0, l1);
    }
}

// ===========================================================================
// Softmax: 2 rows per block (128 threads each), float4 per thread.
// Writes single fp16 plane g_Pf.
// ===========================================================================
__global__ void softmax_kernel()
{
    const int half = threadIdx.x >> 7;        // 0 or 1
    const int t    = threadIdx.x & 127;
    const size_t row = (size_t)blockIdx.x * 2 + half;
    const float* p = g_P + row * 512;

    float4 v = reinterpret_cast<const float4*>(p)[t];
    __shared__ float red[2][4];

    float m = fmaxf(fmaxf(v.x, v.y), fmaxf(v.z, v.w));
#pragma unroll
    for (int o = 16; o > 0; o >>= 1) m = fmaxf(m, __shfl_xor_sync(0xFFFFFFFFu, m, o));
    if ((t & 31) == 0) red[half][t >> 5] = m;
    __syncthreads();
    m = fmaxf(fmaxf(red[half][0], red[half][1]), fmaxf(red[half][2], red[half][3]));
    __syncthreads();

    const float e0 = __expf(v.x - m);
    const float e1 = __expf(v.y - m);
    const float e2 = __expf(v.z - m);
    const float e3 = __expf(v.w - m);

    float s = (e0 + e1) + (e2 + e3);
#pragma unroll
    for (int o = 16; o > 0; o >>= 1) s += __shfl_xor_sync(0xFFFFFFFFu, s, o);
    if ((t & 31) == 0) red[half][t >> 5] = s;
    __syncthreads();
    s = (red[half][0] + red[half][1]) + (red[half][2] + red[half][3]);

    const float inv = 1.0f / s;
    __half2* dst = reinterpret_cast<__half2*>(g_Pf + row * 512);
    dst[t * 2]     = __floats2half2_rn(e0 * inv, e1 * inv);
    dst[t * 2 + 1] = __floats2half2_rn(e2 * inv, e3 * inv);
}

// ===========================================================================
// Launch
// ===========================================================================
extern "C" void kernel_launch(void* const* d_in, const int* in_sizes, int n_in,
                              void* d_out, int out_size)
{
    const float* x  = (const float*)d_in[0];
    const float* wq = (const float*)d_in[1];
    const float* wk = (const float*)d_in[2];
    const float* wv = (const float*)d_in[3];
    float* out = (float*)d_out;

    cudaFuncSetAttribute(gt_wtv,  cudaFuncAttributeMaxDynamicSharedMemorySize, GEMM_SMEM);
    cudaFuncSetAttribute(y_projv, cudaFuncAttributeMaxDynamicSharedMemorySize, GEMM_SMEM);
    cudaFuncSetAttribute(qk2_mm,  cudaFuncAttributeMaxDynamicSharedMemorySize, GEMM_SMEM);
    cudaFuncSetAttribute(pv_mm,   cudaFuncAttributeMaxDynamicSharedMemorySize, GEMM_SMEM);

    prep_split<<<8192, 256>>>(x, wq, wk);                        // 1
    gt_wtv<<<2304, 256, GEMM_SMEM>>>(wv);                        // 2 (gt + wt_v)
    y_projv<<<8192, 256, GEMM_SMEM>>>();                         // 3
    qk2_mm<<<dim3(8, 4, 128), 256, GEMM_SMEM>>>();               // 4 <- profiled
    softmax_kernel<<<32768, 256>>>();                            // 5
    pv_mm<<<dim3(8, 4, 128), 256, GEMM_SMEM>>>(out);             // 6
}